// round 6
// baseline (speedup 1.0000x reference)
#include <cuda_runtime.h>
#include <cuda_fp16.h>
#include <cuda_bf16.h>
#include <math.h>

#define NN 100000
#define EG 600000
#define EE 600000

// ---------------- scratch (static device globals; no allocation) ----------------
__device__ float g_h[NN * 64];
__device__ float g_x[NN * 64];
__device__ float g_out[NN * 64];
__device__ float g_as[NN];
__device__ float g_ad[NN];
__device__ float g_denom[NN];
__device__ __half g_Yh[(size_t)NN * 1040];

__device__ __forceinline__ float fast_elu(float v) {
    return (v > 0.0f) ? v : (__expf(v) - 1.0f);
}

__global__ void zero_scratch() {
    int i = blockIdx.x * blockDim.x + threadIdx.x;
    if (i < NN * 64) g_out[i] = 0.0f;
    if (i < NN) g_denom[i] = 0.0f;
}

// h = x @ W ; a_s = sum(h*att_s) ; a_d = sum(h*att_d)
template <bool FIRST>
__global__ void node_transform(const float* __restrict__ xin,
                               const float* __restrict__ W,
                               const float* __restrict__ att_s,
                               const float* __restrict__ att_d) {
    const int IN = FIRST ? 3 : 64;
    __shared__ float Ws[64 * 64];
    __shared__ float xs[4][64];
    __shared__ float red_s[4][2];
    __shared__ float red_d[4][2];
    int tid = threadIdx.x; // 256
    for (int i = tid; i < IN * 64; i += 256) Ws[i] = W[i];
    int node0 = blockIdx.x * 4;
    for (int i = tid; i < 4 * IN; i += 256) {
        int g = i / IN, k = i % IN;
        int n = node0 + g;
        const float* src = FIRST ? xin : g_x;
        xs[g][k] = (n < NN) ? src[(size_t)n * IN + k] : 0.0f;
    }
    __syncthreads();
    int c = tid & 63;
    int g = tid >> 6;
    int n = node0 + g;
    float v = 0.0f;
#pragma unroll
    for (int k = 0; k < IN; k++) v = fmaf(xs[g][k], Ws[k * 64 + c], v);
    float ps = v * att_s[c];
    float pd = v * att_d[c];
#pragma unroll
    for (int o = 16; o; o >>= 1) {
        ps += __shfl_down_sync(0xFFFFFFFFu, ps, o);
        pd += __shfl_down_sync(0xFFFFFFFFu, pd, o);
    }
    if ((tid & 31) == 0) { red_s[g][c >> 5] = ps; red_d[g][c >> 5] = pd; }
    if (n < NN) g_h[(size_t)n * 64 + c] = v;
    __syncthreads();
    if (n < NN && c == 0) {
        g_as[n] = red_s[g][0] + red_s[g][1];
        g_ad[n] = red_d[g][0] + red_d[g][1];
    }
}

// Fused attention + scatter: one EG pass.
// out[d] += e * h[s]  (unnormalized; finalize divides by denom)
// 16 threads per edge; group leader computes e and the denom atomic, then broadcasts.
__global__ void edge_attn_scatter(const int* __restrict__ gsrc, const int* __restrict__ gdst) {
    long long idx = (long long)blockIdx.x * blockDim.x + threadIdx.x;
    int e = (int)(idx >> 4);
    if (e >= EG) return;
    int l = (int)(idx & 15);
    int lane = threadIdx.x & 31;
    unsigned mask = (lane < 16) ? 0x0000FFFFu : 0xFFFF0000u;
    int s = gsrc[e], d = gdst[e];
    float ev = 0.0f;
    if (l == 0) {
        float a = g_as[s] + g_ad[d];
        a = (a >= 0.0f) ? a : 0.2f * a;
        ev = __expf(a);
        atomicAdd(&g_denom[d], ev);
    }
    ev = __shfl_sync(mask, ev, lane & 16);
    float4 h = ((const float4*)(g_h + (size_t)s * 64))[l];
    float* od = g_out + (size_t)d * 64 + 4 * l;
    asm volatile("red.global.add.v4.f32 [%0], {%1,%2,%3,%4};"
                 :: "l"(od), "f"(h.x * ev), "f"(h.y * ev), "f"(h.z * ev), "f"(h.w * ev) : "memory");
}

// normalize by denom, add bias, ELU
__global__ void finalize_node(const float* __restrict__ bias) {
    int i = blockIdx.x * blockDim.x + threadIdx.x;
    if (i >= NN * 64) return;
    float inv = 1.0f / (g_denom[i >> 6] + 1e-16f);
    g_x[i] = fast_elu(fmaf(g_out[i], inv, bias[i & 63]));
}

// ---------------- tf32 tensor-core GEMM: Y[N,1040] = x[N,64] @ B[64,1040] -------
// M-tile = 128, N-tile = 64. B[k][n<520]=Wm1[k][n]; B[k][n>=520]=Wm1[64+k][n-520].

__device__ __forceinline__ unsigned f2tf32(float f) {
    unsigned r; asm("cvt.rna.tf32.f32 %0, %1;" : "=r"(r) : "f"(f)); return r;
}

__device__ __forceinline__ void mma_tf32(float c[4],
                                         unsigned a0, unsigned a1, unsigned a2, unsigned a3,
                                         unsigned b0, unsigned b1) {
    asm volatile("mma.sync.aligned.m16n8k8.row.col.f32.tf32.tf32.f32 "
                 "{%0,%1,%2,%3}, {%4,%5,%6,%7}, {%8,%9}, {%0,%1,%2,%3};"
                 : "+f"(c[0]), "+f"(c[1]), "+f"(c[2]), "+f"(c[3])
                 : "r"(a0), "r"(a1), "r"(a2), "r"(a3), "r"(b0), "r"(b1));
}

#define GST 68  // smem row stride in words (bank-conflict-free for quad-pair access)

__global__ void gemm_y_tc(const float* __restrict__ Wm1) {
    __shared__ unsigned As[128 * GST];  // 128 rows (M) x 64 (K)
    __shared__ unsigned Bs[64 * GST];   // 64 rows (K) x 64 (N)
    int bm = blockIdx.y, bn = blockIdx.x;
    int tid = threadIdx.x; // 256
    int m0 = bm * 128, n0 = bn * 64;

    for (int i = tid; i < 128 * 16; i += 256) {
        int r = i >> 4, v = i & 15;
        int m = m0 + r;
        float4 x = (m < NN) ? ((const float4*)g_x)[(size_t)m * 16 + v]
                            : make_float4(0.f, 0.f, 0.f, 0.f);
        unsigned* dst = &As[r * GST + v * 4];
        dst[0] = f2tf32(x.x); dst[1] = f2tf32(x.y); dst[2] = f2tf32(x.z); dst[3] = f2tf32(x.w);
    }
    for (int i = tid; i < 64 * 64; i += 256) {
        int k = i >> 6, nl = i & 63;
        int n = n0 + nl;
        float b = 0.0f;
        if (n < 1040) b = (n < 520) ? Wm1[k * 520 + n] : Wm1[(64 + k) * 520 + (n - 520)];
        Bs[k * GST + nl] = f2tf32(b);
    }
    __syncthreads();

    int warp = tid >> 5, lane = tid & 31;
    int wm = warp * 16;          // each warp owns 16 M-rows, all 64 N-cols
    int g = lane >> 2, t = lane & 3;

    float c[8][4];
#pragma unroll
    for (int ni = 0; ni < 8; ni++)
#pragma unroll
        for (int j = 0; j < 4; j++) c[ni][j] = 0.0f;

#pragma unroll
    for (int k8 = 0; k8 < 8; k8++) {
        int kb = k8 * 8;
        unsigned a0 = As[(wm + g) * GST + kb + t];
        unsigned a1 = As[(wm + g + 8) * GST + kb + t];
        unsigned a2 = As[(wm + g) * GST + kb + t + 4];
        unsigned a3 = As[(wm + g + 8) * GST + kb + t + 4];
#pragma unroll
        for (int ni = 0; ni < 8; ni++) {
            int nb = ni * 8;
            unsigned b0 = Bs[(kb + t) * GST + nb + g];
            unsigned b1 = Bs[(kb + t + 4) * GST + nb + g];
            mma_tf32(c[ni], a0, a1, a2, a3, b0, b1);
        }
    }

#pragma unroll
    for (int ni = 0; ni < 8; ni++) {
        int col = n0 + ni * 8 + t * 2;
        if (col >= 1040) continue;
        int r0 = m0 + wm + g;
        int r1 = r0 + 8;
        if (r0 < NN)
            *(__half2*)(g_Yh + (size_t)r0 * 1040 + col) = __floats2half2_rn(c[ni][0], c[ni][1]);
        if (r1 < NN)
            *(__half2*)(g_Yh + (size_t)r1 * 1040 + col) = __floats2half2_rn(c[ni][2], c[ni][3]);
    }
}

// warp per prediction edge; 64 uint4 main (2/lane) + 8-half tail on lanes 0-7
__global__ void edge_mlp(const int* __restrict__ esrc, const int* __restrict__ edst,
                         const float* __restrict__ ea,
                         const float* __restrict__ Wm1, const float* __restrict__ bm1,
                         const float* __restrict__ Wm2, const float* __restrict__ bm2,
                         float* __restrict__ out) {
    __shared__ float sB[520], sW2[520], sC0[520], sC1[520];
    int tid = threadIdx.x; // 256
    for (int i = tid; i < 520; i += 256) {
        sB[i]  = bm1[i];
        sW2[i] = Wm2[i];
        sC0[i] = Wm1[128 * 520 + i];
        sC1[i] = Wm1[129 * 520 + i];
    }
    __syncthreads();
    int e = (blockIdx.x * 256 + tid) >> 5;
    if (e >= EE) return;
    int lane = tid & 31;
    int s = esrc[e], d = edst[e];
    float a0 = ea[2 * e], a1 = ea[2 * e + 1];
    const __half* ysrow = g_Yh + (size_t)s * 1040;
    const __half* ydrow = g_Yh + (size_t)d * 1040 + 520;
    const uint4* ys = (const uint4*)ysrow;
    const uint4* yd = (const uint4*)ydrow;
    float acc = 0.0f;
#pragma unroll
    for (int it = 0; it < 2; it++) {
        int k = lane + it * 32;           // 0..63
        uint4 va = ys[k];
        uint4 vb = yd[k];
        const __half2* ha = (const __half2*)&va;
        const __half2* hb = (const __half2*)&vb;
        int ch = k * 8;
#pragma unroll
        for (int j = 0; j < 4; j++) {
            float2 fa = __half22float2(ha[j]);
            float2 fb = __half22float2(hb[j]);
            int ci = ch + j * 2;
            float v0 = fmaf(a1, sC1[ci],     fmaf(a0, sC0[ci],     fa.x + fb.x + sB[ci]));
            float v1 = fmaf(a1, sC1[ci + 1], fmaf(a0, sC0[ci + 1], fa.y + fb.y + sB[ci + 1]));
            acc = fmaf(fast_elu(v0), sW2[ci], acc);
            acc = fmaf(fast_elu(v1), sW2[ci + 1], acc);
        }
    }
    if (lane < 4) {                        // tail: channels 512..519 as 4 half2
        int ci = 512 + lane * 2;
        float2 fa = __half22float2(*(const __half2*)(ysrow + ci));
        float2 fb = __half22float2(*(const __half2*)(ydrow + ci));
        float v0 = fmaf(a1, sC1[ci],     fmaf(a0, sC0[ci],     fa.x + fb.x + sB[ci]));
        float v1 = fmaf(a1, sC1[ci + 1], fmaf(a0, sC0[ci + 1], fa.y + fb.y + sB[ci + 1]));
        acc = fmaf(fast_elu(v0), sW2[ci], acc);
        acc = fmaf(fast_elu(v1), sW2[ci + 1], acc);
    }
#pragma unroll
    for (int o = 16; o; o >>= 1) acc += __shfl_down_sync(0xFFFFFFFFu, acc, o);
    if (lane == 0) out[e] = acc + bm2[0];
}

static void run_gat_layer(const float* xin, bool first,
                          const float* W, const float* as, const float* ad, const float* b,
                          const int* gsrc, const int* gdst) {
    zero_scratch<<<(NN * 64 + 255) / 256, 256>>>();
    if (first) node_transform<true><<<(NN + 3) / 4, 256>>>(xin, W, as, ad);
    else       node_transform<false><<<(NN + 3) / 4, 256>>>(xin, W, as, ad);
    edge_attn_scatter<<<((long long)EG * 16 + 255) / 256, 256>>>(gsrc, gdst);
    finalize_node<<<(NN * 64 + 255) / 256, 256>>>(b);
}

extern "C" void kernel_launch(void* const* d_in, const int* in_sizes, int n_in,
                              void* d_out, int out_size) {
    const float* pos   = (const float*)d_in[0];
    const int*   eidx  = (const int*)d_in[1];
    const int*   geidx = (const int*)d_in[2];
    const float* eattr = (const float*)d_in[3];
    const float* W0    = (const float*)d_in[4];
    const float* as0   = (const float*)d_in[5];
    const float* ad0   = (const float*)d_in[6];
    const float* b0    = (const float*)d_in[7];
    const float* W1    = (const float*)d_in[8];
    const float* as1   = (const float*)d_in[9];
    const float* ad1   = (const float*)d_in[10];
    const float* b1    = (const float*)d_in[11];
    const float* Wm1   = (const float*)d_in[12];
    const float* bm1   = (const float*)d_in[13];
    const float* Wm2   = (const float*)d_in[14];
    const float* bm2   = (const float*)d_in[15];
    float* out = (float*)d_out;

    const int* gsrc = geidx;
    const int* gdst = geidx + EG;
    const int* esrc = eidx;
    const int* edst = eidx + EE;

    run_gat_layer(pos, true,  W0, as0, ad0, b0, gsrc, gdst);
    run_gat_layer(nullptr, false, W1, as1, ad1, b1, gsrc, gdst);

    dim3 ggrid(17, (NN + 127) / 128);
    gemm_y_tc<<<ggrid, 256>>>(Wm1);

    edge_mlp<<<((long long)EE * 32 + 255) / 256, 256>>>(esrc, edst, eattr, Wm1, bm1, Wm2, bm2, out);
}

// round 8
// speedup vs baseline: 1.5444x; 1.5444x over previous
#include <cuda_runtime.h>
#include <cuda_fp16.h>
#include <cuda_bf16.h>
#include <math.h>

#define NN 100000
#define EG 600000
#define EE 600000

// ---------------- scratch (static device globals; no allocation) ----------------
__device__ __align__(16) __half g_hh[NN * 64];   // fp16 h: halves scatter gather traffic
__device__ float g_x[NN * 64];
__device__ float g_out[NN * 64];
__device__ float g_as[NN];
__device__ float g_ad[NN];
__device__ float g_denom[NN];
__device__ float g_alpha[EG];
__device__ __align__(16) __half g_Yh[(size_t)NN * 1040];

__device__ __forceinline__ float fast_elu(float v) {
    return (v > 0.0f) ? v : (__expf(v) - 1.0f);
}

__global__ void zero_scratch() {
    int i = blockIdx.x * blockDim.x + threadIdx.x;
    if (i < NN * 64) g_out[i] = 0.0f;
    if (i < NN) g_denom[i] = 0.0f;
}

// h = x @ W ; a_s = sum(h*att_s) ; a_d = sum(h*att_d). h stored fp16.
template <bool FIRST>
__global__ void node_transform(const float* __restrict__ xin,
                               const float* __restrict__ W,
                               const float* __restrict__ att_s,
                               const float* __restrict__ att_d) {
    const int IN = FIRST ? 3 : 64;
    __shared__ float Ws[64 * 64];
    __shared__ float xs[4][64];
    __shared__ float red_s[4][2];
    __shared__ float red_d[4][2];
    int tid = threadIdx.x; // 256
    for (int i = tid; i < IN * 64; i += 256) Ws[i] = W[i];
    int node0 = blockIdx.x * 4;
    for (int i = tid; i < 4 * IN; i += 256) {
        int g = i / IN, k = i % IN;
        int n = node0 + g;
        const float* src = FIRST ? xin : g_x;
        xs[g][k] = (n < NN) ? src[(size_t)n * IN + k] : 0.0f;
    }
    __syncthreads();
    int c = tid & 63;
    int g = tid >> 6;
    int n = node0 + g;
    float v = 0.0f;
#pragma unroll
    for (int k = 0; k < IN; k++) v = fmaf(xs[g][k], Ws[k * 64 + c], v);
    float ps = v * att_s[c];
    float pd = v * att_d[c];
#pragma unroll
    for (int o = 16; o; o >>= 1) {
        ps += __shfl_down_sync(0xFFFFFFFFu, ps, o);
        pd += __shfl_down_sync(0xFFFFFFFFu, pd, o);
    }
    if ((tid & 31) == 0) { red_s[g][c >> 5] = ps; red_d[g][c >> 5] = pd; }
    if (n < NN) g_hh[(size_t)n * 64 + c] = __float2half(v);
    __syncthreads();
    if (n < NN && c == 0) {
        g_as[n] = red_s[g][0] + red_s[g][1];
        g_ad[n] = red_d[g][0] + red_d[g][1];
    }
}

// alpha -> leaky_relu -> exp (max shift cancels exactly) -> denom
__global__ void edge_attn(const int* __restrict__ gsrc, const int* __restrict__ gdst) {
    int i = blockIdx.x * blockDim.x + threadIdx.x;
    if (i >= EG) return;
    float a = g_as[gsrc[i]] + g_ad[gdst[i]];
    a = (a >= 0.0f) ? a : 0.2f * a;
    float e = __expf(a);
    g_alpha[i] = e;
    atomicAdd(&g_denom[gdst[i]], e);
}

// 8 threads per edge; each loads 8 halfs (uint4) of h, emits two v4 reductions
__global__ void edge_scatter(const int* __restrict__ gsrc, const int* __restrict__ gdst) {
    long long idx = (long long)blockIdx.x * blockDim.x + threadIdx.x;
    int e = (int)(idx >> 3);
    if (e >= EG) return;
    int l = (int)(idx & 7);
    int s = gsrc[e], d = gdst[e];
    float w = g_alpha[e] / (g_denom[d] + 1e-16f);
    uint4 hv = ((const uint4*)(g_hh + (size_t)s * 64))[l];
    const __half2* hh = (const __half2*)&hv;
    float2 f0 = __half22float2(hh[0]);
    float2 f1 = __half22float2(hh[1]);
    float2 f2 = __half22float2(hh[2]);
    float2 f3 = __half22float2(hh[3]);
    float* od = g_out + (size_t)d * 64 + 8 * l;
    asm volatile("red.global.add.v4.f32 [%0], {%1,%2,%3,%4};"
                 :: "l"(od), "f"(f0.x * w), "f"(f0.y * w), "f"(f1.x * w), "f"(f1.y * w) : "memory");
    asm volatile("red.global.add.v4.f32 [%0], {%1,%2,%3,%4};"
                 :: "l"(od + 4), "f"(f2.x * w), "f"(f2.y * w), "f"(f3.x * w), "f"(f3.y * w) : "memory");
}

__global__ void finalize_node(const float* __restrict__ bias) {
    int i = blockIdx.x * blockDim.x + threadIdx.x;
    if (i >= NN * 64) return;
    g_x[i] = fast_elu(g_out[i] + bias[i & 63]);
}

// ---------------- tf32 tensor-core GEMM: Y[N,1040] = x[N,64] @ B[64,1040] -------
__device__ __forceinline__ unsigned f2tf32(float f) {
    unsigned r; asm("cvt.rna.tf32.f32 %0, %1;" : "=r"(r) : "f"(f)); return r;
}

__device__ __forceinline__ void mma_tf32(float c[4],
                                         unsigned a0, unsigned a1, unsigned a2, unsigned a3,
                                         unsigned b0, unsigned b1) {
    asm volatile("mma.sync.aligned.m16n8k8.row.col.f32.tf32.tf32.f32 "
                 "{%0,%1,%2,%3}, {%4,%5,%6,%7}, {%8,%9}, {%0,%1,%2,%3};"
                 : "+f"(c[0]), "+f"(c[1]), "+f"(c[2]), "+f"(c[3])
                 : "r"(a0), "r"(a1), "r"(a2), "r"(a3), "r"(b0), "r"(b1));
}

#define GST 68

__global__ void gemm_y_tc(const float* __restrict__ Wm1) {
    __shared__ unsigned As[64 * GST];
    __shared__ unsigned Bs[64 * GST];
    int bm = blockIdx.y, bn = blockIdx.x;
    int tid = threadIdx.x; // 256
    int m0 = bm * 64, n0 = bn * 64;

    for (int i = tid; i < 64 * 16; i += 256) {
        int r = i >> 4, v = i & 15;
        int m = m0 + r;
        float4 x = (m < NN) ? ((const float4*)g_x)[(size_t)m * 16 + v]
                            : make_float4(0.f, 0.f, 0.f, 0.f);
        unsigned* dst = &As[r * GST + v * 4];
        dst[0] = f2tf32(x.x); dst[1] = f2tf32(x.y); dst[2] = f2tf32(x.z); dst[3] = f2tf32(x.w);
    }
    for (int i = tid; i < 64 * 64; i += 256) {
        int k = i >> 6, nl = i & 63;
        int n = n0 + nl;
        float b = 0.0f;
        if (n < 1040) b = (n < 520) ? Wm1[k * 520 + n] : Wm1[(64 + k) * 520 + (n - 520)];
        Bs[k * GST + nl] = f2tf32(b);
    }
    __syncthreads();

    int warp = tid >> 5, lane = tid & 31;
    int wm = (warp >> 1) * 16;
    int wn = (warp & 1) * 32;
    int g = lane >> 2, t = lane & 3;

    float c[4][4];
#pragma unroll
    for (int ni = 0; ni < 4; ni++)
#pragma unroll
        for (int j = 0; j < 4; j++) c[ni][j] = 0.0f;

#pragma unroll
    for (int k8 = 0; k8 < 8; k8++) {
        int kb = k8 * 8;
        unsigned a0 = As[(wm + g) * GST + kb + t];
        unsigned a1 = As[(wm + g + 8) * GST + kb + t];
        unsigned a2 = As[(wm + g) * GST + kb + t + 4];
        unsigned a3 = As[(wm + g + 8) * GST + kb + t + 4];
#pragma unroll
        for (int ni = 0; ni < 4; ni++) {
            int nb = wn + ni * 8;
            unsigned b0 = Bs[(kb + t) * GST + nb + g];
            unsigned b1 = Bs[(kb + t + 4) * GST + nb + g];
            mma_tf32(c[ni], a0, a1, a2, a3, b0, b1);
        }
    }

#pragma unroll
    for (int ni = 0; ni < 4; ni++) {
        int col = n0 + wn + ni * 8 + t * 2;
        if (col >= 1040) continue;
        int r0 = m0 + wm + g;
        int r1 = r0 + 8;
        if (r0 < NN)
            *(__half2*)(g_Yh + (size_t)r0 * 1040 + col) = __floats2half2_rn(c[ni][0], c[ni][1]);
        if (r1 < NN)
            *(__half2*)(g_Yh + (size_t)r1 * 1040 + col) = __floats2half2_rn(c[ni][2], c[ni][3]);
    }
}

// warp per prediction edge; HADD2 sum before convert; 64 uint4 main + 4-lane tail
__global__ void edge_mlp(const int* __restrict__ esrc, const int* __restrict__ edst,
                         const float* __restrict__ ea,
                         const float* __restrict__ Wm1, const float* __restrict__ bm1,
                         const float* __restrict__ Wm2, const float* __restrict__ bm2,
                         float* __restrict__ out) {
    __shared__ float sB[520], sW2[520], sC0[520], sC1[520];
    int tid = threadIdx.x; // 256
    for (int i = tid; i < 520; i += 256) {
        sB[i]  = bm1[i];
        sW2[i] = Wm2[i];
        sC0[i] = Wm1[128 * 520 + i];
        sC1[i] = Wm1[129 * 520 + i];
    }
    __syncthreads();
    int e = (blockIdx.x * 256 + tid) >> 5;
    if (e >= EE) return;
    int lane = tid & 31;
    int s = esrc[e], d = edst[e];
    float a0 = ea[2 * e], a1 = ea[2 * e + 1];
    const __half* ysrow = g_Yh + (size_t)s * 1040;
    const __half* ydrow = g_Yh + (size_t)d * 1040 + 520;
    const uint4* ys = (const uint4*)ysrow;
    const uint4* yd = (const uint4*)ydrow;
    float acc = 0.0f;
#pragma unroll
    for (int it = 0; it < 2; it++) {
        int k = lane + it * 32;           // 0..63
        uint4 va = ys[k];
        uint4 vb = yd[k];
        const __half2* ha = (const __half2*)&va;
        const __half2* hb = (const __half2*)&vb;
        int ch = k * 8;
#pragma unroll
        for (int j = 0; j < 4; j++) {
            float2 fs = __half22float2(__hadd2(ha[j], hb[j]));
            int ci = ch + j * 2;
            float v0 = fmaf(a1, sC1[ci],     fmaf(a0, sC0[ci],     fs.x + sB[ci]));
            float v1 = fmaf(a1, sC1[ci + 1], fmaf(a0, sC0[ci + 1], fs.y + sB[ci + 1]));
            acc = fmaf(fast_elu(v0), sW2[ci], acc);
            acc = fmaf(fast_elu(v1), sW2[ci + 1], acc);
        }
    }
    if (lane < 4) {                        // tail: channels 512..519
        int ci = 512 + lane * 2;
        float2 fs = __half22float2(__hadd2(*(const __half2*)(ysrow + ci),
                                           *(const __half2*)(ydrow + ci)));
        float v0 = fmaf(a1, sC1[ci],     fmaf(a0, sC0[ci],     fs.x + sB[ci]));
        float v1 = fmaf(a1, sC1[ci + 1], fmaf(a0, sC0[ci + 1], fs.y + sB[ci + 1]));
        acc = fmaf(fast_elu(v0), sW2[ci], acc);
        acc = fmaf(fast_elu(v1), sW2[ci + 1], acc);
    }
#pragma unroll
    for (int o = 16; o; o >>= 1) acc += __shfl_down_sync(0xFFFFFFFFu, acc, o);
    if (lane == 0) out[e] = acc + bm2[0];
}

static void run_gat_layer(const float* xin, bool first,
                          const float* W, const float* as, const float* ad, const float* b,
                          const int* gsrc, const int* gdst) {
    zero_scratch<<<(NN * 64 + 255) / 256, 256>>>();
    if (first) node_transform<true><<<(NN + 3) / 4, 256>>>(xin, W, as, ad);
    else       node_transform<false><<<(NN + 3) / 4, 256>>>(xin, W, as, ad);
    edge_attn<<<(EG + 255) / 256, 256>>>(gsrc, gdst);
    edge_scatter<<<((long long)EG * 8 + 255) / 256, 256>>>(gsrc, gdst);
    finalize_node<<<(NN * 64 + 255) / 256, 256>>>(b);
}

extern "C" void kernel_launch(void* const* d_in, const int* in_sizes, int n_in,
                              void* d_out, int out_size) {
    const float* pos   = (const float*)d_in[0];
    const int*   eidx  = (const int*)d_in[1];
    const int*   geidx = (const int*)d_in[2];
    const float* eattr = (const float*)d_in[3];
    const float* W0    = (const float*)d_in[4];
    const float* as0   = (const float*)d_in[5];
    const float* ad0   = (const float*)d_in[6];
    const float* b0    = (const float*)d_in[7];
    const float* W1    = (const float*)d_in[8];
    const float* as1   = (const float*)d_in[9];
    const float* ad1   = (const float*)d_in[10];
    const float* b1    = (const float*)d_in[11];
    const float* Wm1   = (const float*)d_in[12];
    const float* bm1   = (const float*)d_in[13];
    const float* Wm2   = (const float*)d_in[14];
    const float* bm2   = (const float*)d_in[15];
    float* out = (float*)d_out;

    const int* gsrc = geidx;
    const int* gdst = geidx + EG;
    const int* esrc = eidx;
    const int* edst = eidx + EE;

    run_gat_layer(pos, true,  W0, as0, ad0, b0, gsrc, gdst);
    run_gat_layer(nullptr, false, W1, as1, ad1, b1, gsrc, gdst);

    dim3 ggrid(17, (NN + 63) / 64);
    gemm_y_tc<<<ggrid, 256>>>(Wm1);

    edge_mlp<<<((long long)EE * 32 + 255) / 256, 256>>>(esrc, edst, eattr, Wm1, bm1, Wm2, bm2, out);
}

// round 10
// speedup vs baseline: 1.8020x; 1.1668x over previous
#include <cuda_runtime.h>
#include <cuda_fp16.h>
#include <cuda_bf16.h>
#include <math.h>

#define NN 100000
#define EG 600000
#define EE 600000

// ---------------- scratch (static device globals; no allocation) ----------------
__device__ __align__(16) __half g_hh[NN * 64];   // fp16 h
__device__ float g_x[NN * 64];
__device__ float g_out[NN * 64];
__device__ float g_as[NN];
__device__ float g_ad[NN];
__device__ float g_denom[NN];
__device__ float g_alpha[EG];
__device__ __align__(16) __half g_Yh[(size_t)NN * 1040];

__device__ __forceinline__ float fast_elu(float v) {
    return (v > 0.0f) ? v : (__expf(v) - 1.0f);
}

// h = x @ W ; a_s = sum(h*att_s) ; a_d = sum(h*att_d). h stored fp16.
// Also zeroes g_out / g_denom for this block's 4 nodes (replaces zero_scratch).
template <bool FIRST>
__global__ void node_transform(const float* __restrict__ xin,
                               const float* __restrict__ W,
                               const float* __restrict__ att_s,
                               const float* __restrict__ att_d) {
    const int IN = FIRST ? 3 : 64;
    __shared__ float Ws[64 * 64];
    __shared__ float xs[4][64];
    __shared__ float red_s[4][2];
    __shared__ float red_d[4][2];
    int tid = threadIdx.x; // 256
    int node0 = blockIdx.x * 4;

    // fused zeroing: 4 nodes x 64 channels = 256 floats, one per thread
    {
        int zn = node0 + (tid >> 6);
        if (zn < NN) g_out[(size_t)zn * 64 + (tid & 63)] = 0.0f;
        if (tid < 4 && node0 + tid < NN) g_denom[node0 + tid] = 0.0f;
    }

    for (int i = tid; i < IN * 64; i += 256) Ws[i] = W[i];
    for (int i = tid; i < 4 * IN; i += 256) {
        int g = i / IN, k = i % IN;
        int n = node0 + g;
        const float* src = FIRST ? xin : g_x;
        xs[g][k] = (n < NN) ? src[(size_t)n * IN + k] : 0.0f;
    }
    __syncthreads();
    int c = tid & 63;
    int g = tid >> 6;
    int n = node0 + g;
    float v = 0.0f;
#pragma unroll
    for (int k = 0; k < IN; k++) v = fmaf(xs[g][k], Ws[k * 64 + c], v);
    float ps = v * att_s[c];
    float pd = v * att_d[c];
#pragma unroll
    for (int o = 16; o; o >>= 1) {
        ps += __shfl_down_sync(0xFFFFFFFFu, ps, o);
        pd += __shfl_down_sync(0xFFFFFFFFu, pd, o);
    }
    if ((tid & 31) == 0) { red_s[g][c >> 5] = ps; red_d[g][c >> 5] = pd; }
    if (n < NN) g_hh[(size_t)n * 64 + c] = __float2half(v);
    __syncthreads();
    if (n < NN && c == 0) {
        g_as[n] = red_s[g][0] + red_s[g][1];
        g_ad[n] = red_d[g][0] + red_d[g][1];
    }
}

// alpha -> leaky_relu -> exp (max shift cancels exactly) -> denom
__global__ void edge_attn(const int* __restrict__ gsrc, const int* __restrict__ gdst) {
    int i = blockIdx.x * blockDim.x + threadIdx.x;
    if (i >= EG) return;
    float a = g_as[gsrc[i]] + g_ad[gdst[i]];
    a = (a >= 0.0f) ? a : 0.2f * a;
    float e = __expf(a);
    g_alpha[i] = e;
    atomicAdd(&g_denom[gdst[i]], e);
}

// 8 threads per edge; each loads 8 halfs (uint4) of h, emits two v4 reductions
__global__ void edge_scatter(const int* __restrict__ gsrc, const int* __restrict__ gdst) {
    long long idx = (long long)blockIdx.x * blockDim.x + threadIdx.x;
    int e = (int)(idx >> 3);
    if (e >= EG) return;
    int l = (int)(idx & 7);
    int s = gsrc[e], d = gdst[e];
    float w = g_alpha[e] / (g_denom[d] + 1e-16f);
    uint4 hv = ((const uint4*)(g_hh + (size_t)s * 64))[l];
    const __half2* hh = (const __half2*)&hv;
    float2 f0 = __half22float2(hh[0]);
    float2 f1 = __half22float2(hh[1]);
    float2 f2 = __half22float2(hh[2]);
    float2 f3 = __half22float2(hh[3]);
    float* od = g_out + (size_t)d * 64 + 8 * l;
    asm volatile("red.global.add.v4.f32 [%0], {%1,%2,%3,%4};"
                 :: "l"(od), "f"(f0.x * w), "f"(f0.y * w), "f"(f1.x * w), "f"(f1.y * w) : "memory");
    asm volatile("red.global.add.v4.f32 [%0], {%1,%2,%3,%4};"
                 :: "l"(od + 4), "f"(f2.x * w), "f"(f2.y * w), "f"(f3.x * w), "f"(f3.y * w) : "memory");
}

// float4-vectorized bias + ELU
__global__ void finalize_node(const float* __restrict__ bias) {
    int i = blockIdx.x * blockDim.x + threadIdx.x;
    if (i >= NN * 16) return;
    float4 o = ((const float4*)g_out)[i];
    float4 b = ((const float4*)bias)[i & 15];
    float4 r;
    r.x = fast_elu(o.x + b.x);
    r.y = fast_elu(o.y + b.y);
    r.z = fast_elu(o.z + b.z);
    r.w = fast_elu(o.w + b.w);
    ((float4*)g_x)[i] = r;
}

// ---------------- tf32 tensor-core GEMM: Y[N,1040] = x[N,64] @ B[64,1040] -------
__device__ __forceinline__ unsigned f2tf32(float f) {
    unsigned r; asm("cvt.rna.tf32.f32 %0, %1;" : "=r"(r) : "f"(f)); return r;
}

__device__ __forceinline__ void mma_tf32(float c[4],
                                         unsigned a0, unsigned a1, unsigned a2, unsigned a3,
                                         unsigned b0, unsigned b1) {
    asm volatile("mma.sync.aligned.m16n8k8.row.col.f32.tf32.tf32.f32 "
                 "{%0,%1,%2,%3}, {%4,%5,%6,%7}, {%8,%9}, {%0,%1,%2,%3};"
                 : "+f"(c[0]), "+f"(c[1]), "+f"(c[2]), "+f"(c[3])
                 : "r"(a0), "r"(a1), "r"(a2), "r"(a3), "r"(b0), "r"(b1));
}

#define GST 68

__global__ void gemm_y_tc(const float* __restrict__ Wm1) {
    __shared__ unsigned As[64 * GST];
    __shared__ unsigned Bs[64 * GST];
    int bm = blockIdx.y, bn = blockIdx.x;
    int tid = threadIdx.x; // 256
    int m0 = bm * 64, n0 = bn * 64;

    for (int i = tid; i < 64 * 16; i += 256) {
        int r = i >> 4, v = i & 15;
        int m = m0 + r;
        float4 x = (m < NN) ? ((const float4*)g_x)[(size_t)m * 16 + v]
                            : make_float4(0.f, 0.f, 0.f, 0.f);
        unsigned* dst = &As[r * GST + v * 4];
        dst[0] = f2tf32(x.x); dst[1] = f2tf32(x.y); dst[2] = f2tf32(x.z); dst[3] = f2tf32(x.w);
    }
    for (int i = tid; i < 64 * 64; i += 256) {
        int k = i >> 6, nl = i & 63;
        int n = n0 + nl;
        float b = 0.0f;
        if (n < 1040) b = (n < 520) ? Wm1[k * 520 + n] : Wm1[(64 + k) * 520 + (n - 520)];
        Bs[k * GST + nl] = f2tf32(b);
    }
    __syncthreads();

    int warp = tid >> 5, lane = tid & 31;
    int wm = (warp >> 1) * 16;
    int wn = (warp & 1) * 32;
    int g = lane >> 2, t = lane & 3;

    float c[4][4];
#pragma unroll
    for (int ni = 0; ni < 4; ni++)
#pragma unroll
        for (int j = 0; j < 4; j++) c[ni][j] = 0.0f;

#pragma unroll
    for (int k8 = 0; k8 < 8; k8++) {
        int kb = k8 * 8;
        unsigned a0 = As[(wm + g) * GST + kb + t];
        unsigned a1 = As[(wm + g + 8) * GST + kb + t];
        unsigned a2 = As[(wm + g) * GST + kb + t + 4];
        unsigned a3 = As[(wm + g + 8) * GST + kb + t + 4];
#pragma unroll
        for (int ni = 0; ni < 4; ni++) {
            int nb = wn + ni * 8;
            unsigned b0 = Bs[(kb + t) * GST + nb + g];
            unsigned b1 = Bs[(kb + t + 4) * GST + nb + g];
            mma_tf32(c[ni], a0, a1, a2, a3, b0, b1);
        }
    }

#pragma unroll
    for (int ni = 0; ni < 4; ni++) {
        int col = n0 + wn + ni * 8 + t * 2;
        if (col >= 1040) continue;
        int r0 = m0 + wm + g;
        int r1 = r0 + 8;
        if (r0 < NN)
            *(__half2*)(g_Yh + (size_t)r0 * 1040 + col) = __floats2half2_rn(c[ni][0], c[ni][1]);
        if (r1 < NN)
            *(__half2*)(g_Yh + (size_t)r1 * 1040 + col) = __floats2half2_rn(c[ni][2], c[ni][3]);
    }
}

// warp per prediction edge. Tables stored TRANSPOSED [8 rows][65 cols]:
// channel ci lives at sT[(ci&7)*65 + (ci>>3)]. In the loop ci = 8k + 2j, so
// index = 130j + k: row is compile-time, col = k → conflict-free LDS.
__global__ void edge_mlp(const int* __restrict__ esrc, const int* __restrict__ edst,
                         const float* __restrict__ ea,
                         const float* __restrict__ Wm1, const float* __restrict__ bm1,
                         const float* __restrict__ Wm2, const float* __restrict__ bm2,
                         float* __restrict__ out) {
    __shared__ float sB[520], sW2[520], sC0[520], sC1[520];
    int tid = threadIdx.x; // 256
    for (int i = tid; i < 520; i += 256) {
        int p = (i & 7) * 65 + (i >> 3);
        sB[p]  = bm1[i];
        sW2[p] = Wm2[i];
        sC0[p] = Wm1[128 * 520 + i];
        sC1[p] = Wm1[129 * 520 + i];
    }
    __syncthreads();
    int e = (blockIdx.x * 256 + tid) >> 5;
    if (e >= EE) return;
    int lane = tid & 31;
    int s = esrc[e], d = edst[e];
    float a0 = ea[2 * e], a1 = ea[2 * e + 1];
    const __half* ysrow = g_Yh + (size_t)s * 1040;
    const __half* ydrow = g_Yh + (size_t)d * 1040 + 520;
    const uint4* ys = (const uint4*)ysrow;
    const uint4* yd = (const uint4*)ydrow;
    float acc = 0.0f;
#pragma unroll
    for (int it = 0; it < 2; it++) {
        int k = lane + it * 32;           // 0..63 (uint4 index = ci>>3)
        uint4 va = ys[k];
        uint4 vb = yd[k];
        const __half2* ha = (const __half2*)&va;
        const __half2* hb = (const __half2*)&vb;
#pragma unroll
        for (int j = 0; j < 4; j++) {
            float2 fs = __half22float2(__hadd2(ha[j], hb[j]));
            int p0 = (2 * j) * 65 + k;        // channel 8k+2j
            int p1 = p0 + 65;                 // channel 8k+2j+1
            float v0 = fmaf(a1, sC1[p0], fmaf(a0, sC0[p0], fs.x + sB[p0]));
            float v1 = fmaf(a1, sC1[p1], fmaf(a0, sC0[p1], fs.y + sB[p1]));
            acc = fmaf(fast_elu(v0), sW2[p0], acc);
            acc = fmaf(fast_elu(v1), sW2[p1], acc);
        }
    }
    if (lane < 4) {                        // tail: channels 512..519 (ci>>3 == 64)
        int ci = 512 + lane * 2;
        float2 fs = __half22float2(__hadd2(*(const __half2*)(ysrow + ci),
                                           *(const __half2*)(ydrow + ci)));
        int p0 = (ci & 7) * 65 + 64;
        int p1 = p0 + 65;
        float v0 = fmaf(a1, sC1[p0], fmaf(a0, sC0[p0], fs.x + sB[p0]));
        float v1 = fmaf(a1, sC1[p1], fmaf(a0, sC0[p1], fs.y + sB[p1]));
        acc = fmaf(fast_elu(v0), sW2[p0], acc);
        acc = fmaf(fast_elu(v1), sW2[p1], acc);
    }
#pragma unroll
    for (int o = 16; o; o >>= 1) acc += __shfl_down_sync(0xFFFFFFFFu, acc, o);
    if (lane == 0) out[e] = acc + bm2[0];
}

static void run_gat_layer(const float* xin, bool first,
                          const float* W, const float* as, const float* ad, const float* b,
                          const int* gsrc, const int* gdst) {
    if (first) node_transform<true><<<(NN + 3) / 4, 256>>>(xin, W, as, ad);
    else       node_transform<false><<<(NN + 3) / 4, 256>>>(xin, W, as, ad);
    edge_attn<<<(EG + 255) / 256, 256>>>(gsrc, gdst);
    edge_scatter<<<((long long)EG * 8 + 255) / 256, 256>>>(gsrc, gdst);
    finalize_node<<<(NN * 16 + 255) / 256, 256>>>(b);
}

extern "C" void kernel_launch(void* const* d_in, const int* in_sizes, int n_in,
                              void* d_out, int out_size) {
    const float* pos   = (const float*)d_in[0];
    const int*   eidx  = (const int*)d_in[1];
    const int*   geidx = (const int*)d_in[2];
    const float* eattr = (const float*)d_in[3];
    const float* W0    = (const float*)d_in[4];
    const float* as0   = (const float*)d_in[5];
    const float* ad0   = (const float*)d_in[6];
    const float* b0    = (const float*)d_in[7];
    const float* W1    = (const float*)d_in[8];
    const float* as1   = (const float*)d_in[9];
    const float* ad1   = (const float*)d_in[10];
    const float* b1    = (const float*)d_in[11];
    const float* Wm1   = (const float*)d_in[12];
    const float* bm1   = (const float*)d_in[13];
    const float* Wm2   = (const float*)d_in[14];
    const float* bm2   = (const float*)d_in[15];
    float* out = (float*)d_out;

    const int* gsrc = geidx;
    const int* gdst = geidx + EG;
    const int* esrc = eidx;
    const int* edst = eidx + EE;

    run_gat_layer(pos, true,  W0, as0, ad0, b0, gsrc, gdst);
    run_gat_layer(nullptr, false, W1, as1, ad1, b1, gsrc, gdst);

    dim3 ggrid(17, (NN + 63) / 64);
    gemm_y_tc<<<ggrid, 256>>>(Wm1);

    edge_mlp<<<((long long)EE * 32 + 255) / 256, 256>>>(esrc, edst, eattr, Wm1, bm1, Wm2, bm2, out);
}

// round 11
// speedup vs baseline: 1.8583x; 1.0313x over previous
#include <cuda_runtime.h>
#include <cuda_fp16.h>
#include <cuda_bf16.h>
#include <math.h>

#define NN 100000
#define EG 600000
#define EE 600000

// ---------------- scratch (static device globals; no allocation) ----------------
__device__ __align__(16) __half g_hh[NN * 64];   // fp16 h
__device__ float g_x[NN * 64];
__device__ float g_out[NN * 64];
__device__ float g_as[NN];
__device__ float g_ad[NN];
__device__ float g_denom[NN];
__device__ float g_alpha[EG];
__device__ __align__(16) __half g_Yh[(size_t)NN * 1040];

__device__ __forceinline__ float fast_elu(float v) {
    return (v > 0.0f) ? v : (__expf(v) - 1.0f);
}

// h = x @ W ; a_s = sum(h*att_s) ; a_d = sum(h*att_d). h stored fp16.
// Also zeroes g_out / g_denom for this block's 4 nodes.
template <bool FIRST>
__global__ void node_transform(const float* __restrict__ xin,
                               const float* __restrict__ W,
                               const float* __restrict__ att_s,
                               const float* __restrict__ att_d) {
    const int IN = FIRST ? 3 : 64;
    __shared__ float Ws[64 * 64];
    __shared__ float xs[4][64];
    __shared__ float red_s[4][2];
    __shared__ float red_d[4][2];
    int tid = threadIdx.x; // 256
    int node0 = blockIdx.x * 4;

    {
        int zn = node0 + (tid >> 6);
        if (zn < NN) g_out[(size_t)zn * 64 + (tid & 63)] = 0.0f;
        if (tid < 4 && node0 + tid < NN) g_denom[node0 + tid] = 0.0f;
    }

    for (int i = tid; i < IN * 64; i += 256) Ws[i] = W[i];
    for (int i = tid; i < 4 * IN; i += 256) {
        int g = i / IN, k = i % IN;
        int n = node0 + g;
        const float* src = FIRST ? xin : g_x;
        xs[g][k] = (n < NN) ? src[(size_t)n * IN + k] : 0.0f;
    }
    __syncthreads();
    int c = tid & 63;
    int g = tid >> 6;
    int n = node0 + g;
    float v = 0.0f;
#pragma unroll
    for (int k = 0; k < IN; k++) v = fmaf(xs[g][k], Ws[k * 64 + c], v);
    float ps = v * att_s[c];
    float pd = v * att_d[c];
#pragma unroll
    for (int o = 16; o; o >>= 1) {
        ps += __shfl_down_sync(0xFFFFFFFFu, ps, o);
        pd += __shfl_down_sync(0xFFFFFFFFu, pd, o);
    }
    if ((tid & 31) == 0) { red_s[g][c >> 5] = ps; red_d[g][c >> 5] = pd; }
    if (n < NN) g_hh[(size_t)n * 64 + c] = __float2half(v);
    __syncthreads();
    if (n < NN && c == 0) {
        g_as[n] = red_s[g][0] + red_s[g][1];
        g_ad[n] = red_d[g][0] + red_d[g][1];
    }
}

// alpha -> leaky_relu -> exp (softmax max-shift cancels exactly) -> denom
__global__ void edge_attn(const int* __restrict__ gsrc, const int* __restrict__ gdst) {
    int i = blockIdx.x * blockDim.x + threadIdx.x;
    if (i >= EG) return;
    float a = g_as[gsrc[i]] + g_ad[gdst[i]];
    a = (a >= 0.0f) ? a : 0.2f * a;
    float e = __expf(a);
    g_alpha[i] = e;
    atomicAdd(&g_denom[gdst[i]], e);
}

// 8 threads per edge; scatter UNNORMALIZED e*h (finalize divides by denom).
// No random denom load / no divide in the atomic hot path.
__global__ void edge_scatter(const int* __restrict__ gsrc, const int* __restrict__ gdst) {
    long long idx = (long long)blockIdx.x * blockDim.x + threadIdx.x;
    int e = (int)(idx >> 3);
    if (e >= EG) return;
    int l = (int)(idx & 7);
    int s = gsrc[e], d = gdst[e];
    float w = g_alpha[e];
    uint4 hv = ((const uint4*)(g_hh + (size_t)s * 64))[l];
    const __half2* hh = (const __half2*)&hv;
    float2 f0 = __half22float2(hh[0]);
    float2 f1 = __half22float2(hh[1]);
    float2 f2 = __half22float2(hh[2]);
    float2 f3 = __half22float2(hh[3]);
    float* od = g_out + (size_t)d * 64 + 8 * l;
    asm volatile("red.global.add.v4.f32 [%0], {%1,%2,%3,%4};"
                 :: "l"(od), "f"(f0.x * w), "f"(f0.y * w), "f"(f1.x * w), "f"(f1.y * w) : "memory");
    asm volatile("red.global.add.v4.f32 [%0], {%1,%2,%3,%4};"
                 :: "l"(od + 4), "f"(f2.x * w), "f"(f2.y * w), "f"(f3.x * w), "f"(f3.y * w) : "memory");
}

// float4-vectorized: normalize by denom, add bias, ELU
__global__ void finalize_node(const float* __restrict__ bias) {
    int i = blockIdx.x * blockDim.x + threadIdx.x;
    if (i >= NN * 16) return;
    float inv = 1.0f / (g_denom[i >> 4] + 1e-16f);
    float4 o = ((const float4*)g_out)[i];
    float4 b = ((const float4*)bias)[i & 15];
    float4 r;
    r.x = fast_elu(fmaf(o.x, inv, b.x));
    r.y = fast_elu(fmaf(o.y, inv, b.y));
    r.z = fast_elu(fmaf(o.z, inv, b.z));
    r.w = fast_elu(fmaf(o.w, inv, b.w));
    ((float4*)g_x)[i] = r;
}

// ---------------- tf32 tensor-core GEMM: Y[N,1040] = x[N,64] @ B[64,1040] -------
__device__ __forceinline__ unsigned f2tf32(float f) {
    unsigned r; asm("cvt.rna.tf32.f32 %0, %1;" : "=r"(r) : "f"(f)); return r;
}

__device__ __forceinline__ void mma_tf32(float c[4],
                                         unsigned a0, unsigned a1, unsigned a2, unsigned a3,
                                         unsigned b0, unsigned b1) {
    asm volatile("mma.sync.aligned.m16n8k8.row.col.f32.tf32.tf32.f32 "
                 "{%0,%1,%2,%3}, {%4,%5,%6,%7}, {%8,%9}, {%0,%1,%2,%3};"
                 : "+f"(c[0]), "+f"(c[1]), "+f"(c[2]), "+f"(c[3])
                 : "r"(a0), "r"(a1), "r"(a2), "r"(a3), "r"(b0), "r"(b1));
}

#define GST 68

__global__ void gemm_y_tc(const float* __restrict__ Wm1) {
    __shared__ unsigned As[64 * GST];
    __shared__ unsigned Bs[64 * GST];
    int bm = blockIdx.y, bn = blockIdx.x;
    int tid = threadIdx.x; // 256
    int m0 = bm * 64, n0 = bn * 64;

    for (int i = tid; i < 64 * 16; i += 256) {
        int r = i >> 4, v = i & 15;
        int m = m0 + r;
        float4 x = (m < NN) ? ((const float4*)g_x)[(size_t)m * 16 + v]
                            : make_float4(0.f, 0.f, 0.f, 0.f);
        unsigned* dst = &As[r * GST + v * 4];
        dst[0] = f2tf32(x.x); dst[1] = f2tf32(x.y); dst[2] = f2tf32(x.z); dst[3] = f2tf32(x.w);
    }
    for (int i = tid; i < 64 * 64; i += 256) {
        int k = i >> 6, nl = i & 63;
        int n = n0 + nl;
        float b = 0.0f;
        if (n < 1040) b = (n < 520) ? Wm1[k * 520 + n] : Wm1[(64 + k) * 520 + (n - 520)];
        Bs[k * GST + nl] = f2tf32(b);
    }
    __syncthreads();

    int warp = tid >> 5, lane = tid & 31;
    int wm = (warp >> 1) * 16;
    int wn = (warp & 1) * 32;
    int g = lane >> 2, t = lane & 3;

    float c[4][4];
#pragma unroll
    for (int ni = 0; ni < 4; ni++)
#pragma unroll
        for (int j = 0; j < 4; j++) c[ni][j] = 0.0f;

#pragma unroll
    for (int k8 = 0; k8 < 8; k8++) {
        int kb = k8 * 8;
        unsigned a0 = As[(wm + g) * GST + kb + t];
        unsigned a1 = As[(wm + g + 8) * GST + kb + t];
        unsigned a2 = As[(wm + g) * GST + kb + t + 4];
        unsigned a3 = As[(wm + g + 8) * GST + kb + t + 4];
#pragma unroll
        for (int ni = 0; ni < 4; ni++) {
            int nb = wn + ni * 8;
            unsigned b0 = Bs[(kb + t) * GST + nb + g];
            unsigned b1 = Bs[(kb + t + 4) * GST + nb + g];
            mma_tf32(c[ni], a0, a1, a2, a3, b0, b1);
        }
    }

#pragma unroll
    for (int ni = 0; ni < 4; ni++) {
        int col = n0 + wn + ni * 8 + t * 2;
        if (col >= 1040) continue;
        int r0 = m0 + wm + g;
        int r1 = r0 + 8;
        if (r0 < NN)
            *(__half2*)(g_Yh + (size_t)r0 * 1040 + col) = __floats2half2_rn(c[ni][0], c[ni][1]);
        if (r1 < NN)
            *(__half2*)(g_Yh + (size_t)r1 * 1040 + col) = __floats2half2_rn(c[ni][2], c[ni][3]);
    }
}

// warp per prediction edge. All four per-channel tables (bm1, C0=Wm1 row128,
// C1=Wm1 row129, W2) packed fp16 into ONE uint4 per (j,k): 1 LDS.128 replaces
// 8 LDS.32 per iteration. Layout: sT[(j*65+k)*8 + {0,1:B, 2,3:C0, 4,5:C1, 6,7:W2}]
// where channel ci = 8k + 2j + parity.
__global__ void edge_mlp(const int* __restrict__ esrc, const int* __restrict__ edst,
                         const float* __restrict__ ea,
                         const float* __restrict__ Wm1, const float* __restrict__ bm1,
                         const float* __restrict__ Wm2, const float* __restrict__ bm2,
                         float* __restrict__ out) {
    __shared__ __align__(16) __half sT[4 * 65 * 8];
    int tid = threadIdx.x; // 256
    for (int i = tid; i < 520; i += 256) {
        int k = i >> 3, j = (i & 7) >> 1, par = i & 1;
        int base = (j * 65 + k) * 8 + par;
        sT[base + 0] = __float2half(bm1[i]);
        sT[base + 2] = __float2half(Wm1[128 * 520 + i]);
        sT[base + 4] = __float2half(Wm1[129 * 520 + i]);
        sT[base + 6] = __float2half(Wm2[i]);
    }
    __syncthreads();
    const uint4* sTv = (const uint4*)sT;
    int e = (blockIdx.x * 256 + tid) >> 5;
    if (e >= EE) return;
    int lane = tid & 31;
    int s = esrc[e], d = edst[e];
    float a0 = ea[2 * e], a1 = ea[2 * e + 1];
    const __half* ysrow = g_Yh + (size_t)s * 1040;
    const __half* ydrow = g_Yh + (size_t)d * 1040 + 520;
    const uint4* ys = (const uint4*)ysrow;
    const uint4* yd = (const uint4*)ydrow;
    float acc = 0.0f;
#pragma unroll
    for (int it = 0; it < 2; it++) {
        int k = lane + it * 32;           // 0..63
        uint4 va = ys[k];
        uint4 vb = yd[k];
        const __half2* ha = (const __half2*)&va;
        const __half2* hb = (const __half2*)&vb;
#pragma unroll
        for (int j = 0; j < 4; j++) {
            uint4 tv = sTv[j * 65 + k];
            const __half2* th = (const __half2*)&tv;
            float2 fs = __half22float2(__hadd2(ha[j], hb[j]));
            float2 Bf  = __half22float2(th[0]);
            float2 C0f = __half22float2(th[1]);
            float2 C1f = __half22float2(th[2]);
            float2 W2f = __half22float2(th[3]);
            float v0 = fmaf(a1, C1f.x, fmaf(a0, C0f.x, fs.x + Bf.x));
            float v1 = fmaf(a1, C1f.y, fmaf(a0, C0f.y, fs.y + Bf.y));
            acc = fmaf(fast_elu(v0), W2f.x, acc);
            acc = fmaf(fast_elu(v1), W2f.y, acc);
        }
    }
    if (lane < 4) {                        // tail: channels 512..519 (k=64, j=lane)
        int ci = 512 + lane * 2;
        uint4 tv = sTv[lane * 65 + 64];
        const __half2* th = (const __half2*)&tv;
        float2 fs = __half22float2(__hadd2(*(const __half2*)(ysrow + ci),
                                           *(const __half2*)(ydrow + ci)));
        float2 Bf  = __half22float2(th[0]);
        float2 C0f = __half22float2(th[1]);
        float2 C1f = __half22float2(th[2]);
        float2 W2f = __half22float2(th[3]);
        float v0 = fmaf(a1, C1f.x, fmaf(a0, C0f.x, fs.x + Bf.x));
        float v1 = fmaf(a1, C1f.y, fmaf(a0, C0f.y, fs.y + Bf.y));
        acc = fmaf(fast_elu(v0), W2f.x, acc);
        acc = fmaf(fast_elu(v1), W2f.y, acc);
    }
#pragma unroll
    for (int o = 16; o; o >>= 1) acc += __shfl_down_sync(0xFFFFFFFFu, acc, o);
    if (lane == 0) out[e] = acc + bm2[0];
}

static void run_gat_layer(const float* xin, bool first,
                          const float* W, const float* as, const float* ad, const float* b,
                          const int* gsrc, const int* gdst) {
    if (first) node_transform<true><<<(NN + 3) / 4, 256>>>(xin, W, as, ad);
    else       node_transform<false><<<(NN + 3) / 4, 256>>>(xin, W, as, ad);
    edge_attn<<<(EG + 255) / 256, 256>>>(gsrc, gdst);
    edge_scatter<<<((long long)EG * 8 + 255) / 256, 256>>>(gsrc, gdst);
    finalize_node<<<(NN * 16 + 255) / 256, 256>>>(b);
}

extern "C" void kernel_launch(void* const* d_in, const int* in_sizes, int n_in,
                              void* d_out, int out_size) {
    const float* pos   = (const float*)d_in[0];
    const int*   eidx  = (const int*)d_in[1];
    const int*   geidx = (const int*)d_in[2];
    const float* eattr = (const float*)d_in[3];
    const float* W0    = (const float*)d_in[4];
    const float* as0   = (const float*)d_in[5];
    const float* ad0   = (const float*)d_in[6];
    const float* b0    = (const float*)d_in[7];
    const float* W1    = (const float*)d_in[8];
    const float* as1   = (const float*)d_in[9];
    const float* ad1   = (const float*)d_in[10];
    const float* b1    = (const float*)d_in[11];
    const float* Wm1   = (const float*)d_in[12];
    const float* bm1   = (const float*)d_in[13];
    const float* Wm2   = (const float*)d_in[14];
    const float* bm2   = (const float*)d_in[15];
    float* out = (float*)d_out;

    const int* gsrc = geidx;
    const int* gdst = geidx + EG;
    const int* esrc = eidx;
    const int* edst = eidx + EE;

    run_gat_layer(pos, true,  W0, as0, ad0, b0, gsrc, gdst);
    run_gat_layer(nullptr, false, W1, as1, ad1, b1, gsrc, gdst);

    dim3 ggrid(17, (NN + 63) / 64);
    gemm_y_tc<<<ggrid, 256>>>(Wm1);

    edge_mlp<<<((long long)EE * 32 + 255) / 256, 256>>>(esrc, edst, eattr, Wm1, bm1, Wm2, bm2, out);
}